// round 8
// baseline (speedup 1.0000x reference)
#include <cuda_runtime.h>

// ---------------------------------------------------------------------------
// QRU forward, S=512, B=256, IN_Q=64, H=64.  Round 6: FFMA2 with low-pressure
// thread mapping (r in lane index; 8 g-cols/thread; 4p in registers).
//
// 128 persistent CTAs (1/SM), 512 threads, each CTA owns 2 batch rows for all
// 512 steps. Per step: two quaternion dual-matmuls (phase A/B) decomposed into
// per-component partial dots d[p][c][ks][r][g] + 16-entry Hamilton sign
// combine.
//
// Dot-phase thread map: t = c(2b) | ks(2b) | gv(4b) | r(1b).
//   warp = (c,ks) fixed; lanes span 16 gv x 2 r.
//   Each thread: r fixed, g-cols [gv*8, gv*8+8), k in [ks*32, ks*32+32), all p.
//   acc: 4p x 4 u64 pairs = 32 regs. Per k-pair: 4 LDS.128 (dup'd v broadcast),
//   4 LDG.128 (W, dedup'd across r-lane pairs), 32 FMA2.
// ---------------------------------------------------------------------------

__device__ float g_WA[4 * 128 * 128];   // phase A: k<64 -> w_ih, k>=64 -> w_hh
__device__ float g_WB[4 * 128 * 128];   // phase B: k<64 -> wpick_h, k>=64 -> wpick_cand
__device__ float g_bA[512];             // b_ih + b_hh
__device__ float g_bB[512];             // b_pick_h + b_pick_cand

__constant__ int   c_M[16] = {0,1,2,3,  1,0,3,2,  2,3,0,1,  3,2,1,0};
__constant__ float c_S[16] = {1.f,-1.f,-1.f,-1.f,  1.f,1.f,-1.f,1.f,
                              1.f,1.f,1.f,-1.f,    1.f,-1.f,1.f,1.f};

#define FMA2(acc, a, b) \
    asm("fma.rn.f32x2 %0, %1, %2, %0;" : "+l"(acc) : "l"(a), "l"(b))

// --- prep: repack weights + fold biases (runs once per launch) -------------
__global__ void qru_prep(
    const float* __restrict__ wih_r, const float* __restrict__ wih_i,
    const float* __restrict__ wih_j, const float* __restrict__ wih_k,
    const float* __restrict__ whh_r, const float* __restrict__ whh_i,
    const float* __restrict__ whh_j, const float* __restrict__ whh_k,
    const float* __restrict__ wpc_r, const float* __restrict__ wpc_i,
    const float* __restrict__ wpc_j, const float* __restrict__ wpc_k,
    const float* __restrict__ wph_r, const float* __restrict__ wph_i,
    const float* __restrict__ wph_j, const float* __restrict__ wph_k,
    const float* __restrict__ b_ih, const float* __restrict__ b_hh,
    const float* __restrict__ b_ph, const float* __restrict__ b_pc)
{
    int i = blockIdx.x * blockDim.x + threadIdx.x;   // 131072 total
    int half = i >> 16;
    int j = i & 65535;
    int cc = j >> 14;
    int k  = (j >> 7) & 127;
    int gg = j & 127;
    const float* src;
    if (half == 0) {
        if (k < 64) src = (cc == 0 ? wih_r : cc == 1 ? wih_i : cc == 2 ? wih_j : wih_k);
        else        src = (cc == 0 ? whh_r : cc == 1 ? whh_i : cc == 2 ? whh_j : whh_k);
        g_WA[j] = src[(k & 63) * 128 + gg];
    } else {
        if (k < 64) src = (cc == 0 ? wph_r : cc == 1 ? wph_i : cc == 2 ? wph_j : wph_k);
        else        src = (cc == 0 ? wpc_r : cc == 1 ? wpc_i : cc == 2 ? wpc_j : wpc_k);
        g_WB[j] = src[(k & 63) * 128 + gg];
    }
    if (i < 512)            g_bA[i]       = b_ih[i] + b_hh[i];
    else if (i < 1024)      g_bB[i - 512] = b_ph[i - 512] + b_pc[i - 512];
}

// --- dot phase (FFMA2): thread = (c, ks, gv, r); d[p][8 g's] ---------------
__device__ __forceinline__ void qdot2(const float2* __restrict__ v2,   // [2][4][128] dup pairs
                                      const float* __restrict__ W,     // [4][128][128]
                                      float* __restrict__ ds,
                                      int c, int ks, int gv, int r)
{
    unsigned long long acc[4][4];
#pragma unroll
    for (int p = 0; p < 4; ++p)
#pragma unroll
        for (int i = 0; i < 4; ++i) acc[p][i] = 0ULL;

    // ulonglong2 = 4 consecutive g floats; 32 per k row of 128.
    const ulonglong2* Wp =
        reinterpret_cast<const ulonglong2*>(W) + (c * 128 + ks * 32) * 32 + gv * 2;
    const int k0 = ks * 32;
    const float2* vbase = v2 + r * 4 * 128 + k0;

#pragma unroll 2
    for (int kb = 0; kb < 32; kb += 2) {
        ulonglong2 w0a = Wp[0];      // row k : g[0..3]
        ulonglong2 w0b = Wp[1];      // row k : g[4..7]
        ulonglong2 w1a = Wp[32];     // row k+1 : g[0..3]
        ulonglong2 w1b = Wp[33];     // row k+1 : g[4..7]
        Wp += 64;
#pragma unroll
        for (int p = 0; p < 4; ++p) {
            // duplicated broadcast pairs {v_k,v_k},{v_k1,v_k1}
            const ulonglong2 vd = *reinterpret_cast<const ulonglong2*>(
                vbase + p * 128 + kb);
            FMA2(acc[p][0], vd.x, w0a.x);
            FMA2(acc[p][1], vd.x, w0a.y);
            FMA2(acc[p][2], vd.x, w0b.x);
            FMA2(acc[p][3], vd.x, w0b.y);
            FMA2(acc[p][0], vd.y, w1a.x);
            FMA2(acc[p][1], vd.y, w1a.y);
            FMA2(acc[p][2], vd.y, w1b.x);
            FMA2(acc[p][3], vd.y, w1b.y);
        }
    }
#pragma unroll
    for (int p = 0; p < 4; ++p) {
        float* d = ds + (p * 4 + c) * 1024 + ks * 256 + r * 128 + gv * 8;
        ulonglong2 o1; o1.x = acc[p][0]; o1.y = acc[p][1];
        ulonglong2 o2; o2.x = acc[p][2]; o2.y = acc[p][3];
        *reinterpret_cast<ulonglong2*>(d)     = o1;
        *reinterpret_cast<ulonglong2*>(d + 4) = o2;
    }
}

// --- sign combine: thread = (q, g) -----------------------------------------
__device__ __forceinline__ void qcombine(const float* __restrict__ ds,
                                         const float* __restrict__ bias,
                                         float* __restrict__ yb, int q, int g)
{
#pragma unroll
    for (int r = 0; r < 2; ++r) {
        float y = bias[q * 128 + g];
#pragma unroll
        for (int p = 0; p < 4; ++p) {
            const int   cm = c_M[q * 4 + p];
            const float sg = c_S[q * 4 + p];
            const float* dp = ds + (p * 4 + cm) * 1024 + r * 128 + g;   // ks stride = 256
            float sum = dp[0] + dp[256] + dp[512] + dp[768];
            y = fmaf(sg, sum, y);
        }
        yb[r * 512 + q * 128 + g] = y;
    }
}

__global__ void __launch_bounds__(512, 1)
qru_main(const float* __restrict__ x, const float* __restrict__ hx,
         float* __restrict__ out, float* __restrict__ hT, int writeHT)
{
    extern __shared__ float smf[];
    float*  ds  = smf;                              // 16384 : partial dots
    float2* vA2 = (float2*)(smf + 16384);           //  2048f: phase A input dup [r][p][128]
    float2* vB2 = (float2*)(smf + 18432);           //  2048f: phase B input dup
    float*  yb  = smf + 20480;                      //  1024 : combine output [r][512]
    float*  hb  = smf + 21504;                      //   512 : hidden carry   [r][256]

    const int t   = threadIdx.x;
    const int b0  = blockIdx.x * 2;
    const int c   = t >> 7;            // weight component (also q in combine)
    const int ks  = (t >> 5) & 3;      // k-slice
    const int gv  = (t >> 1) & 15;     // 8-wide g group
    const int rq  = t & 1;             // batch row for dot phase
    const int g   = t & 127;           // combine column
    const int rr  = t >> 8;            // x-load row
    const int idx = t & 255;           // x-load feature
    const int xp = idx >> 6, xk = idx & 63;

    hb[rr * 256 + idx] = hx[(b0 + rr) * 256 + idx];
    __syncthreads();

    // x prefetch for step 0
    float xv = x[(size_t)(b0 + rr) * 256 + idx];

    for (int s = 0; s < 512; ++s) {
        // (a) normalize h -> h_n into vA2[k>=64] and vB2[k<64] (duplicated)
        if (t < 128) {
            const int r = t >> 6, n = t & 63;
            float h0 = hb[r * 256 + n],        h1 = hb[r * 256 + 64 + n];
            float h2 = hb[r * 256 + 128 + n],  h3 = hb[r * 256 + 192 + n];
            float inv = 1.f / (sqrtf(h0 * h0 + h1 * h1 + h2 * h2 + h3 * h3) + 1e-4f);
            h0 *= inv; h1 *= inv; h2 *= inv; h3 *= inv;
            vA2[(r * 4 + 0) * 128 + 64 + n] = make_float2(h0, h0);
            vA2[(r * 4 + 1) * 128 + 64 + n] = make_float2(h1, h1);
            vA2[(r * 4 + 2) * 128 + 64 + n] = make_float2(h2, h2);
            vA2[(r * 4 + 3) * 128 + 64 + n] = make_float2(h3, h3);
            vB2[(r * 4 + 0) * 128 + n] = make_float2(h0, h0);
            vB2[(r * 4 + 1) * 128 + n] = make_float2(h1, h1);
            vB2[(r * 4 + 2) * 128 + n] = make_float2(h2, h2);
            vB2[(r * 4 + 3) * 128 + n] = make_float2(h3, h3);
        }
        // (b) write prefetched x_s into vA2[k<64]; issue prefetch for s+1
        vA2[(rr * 4 + xp) * 128 + xk] = make_float2(xv, xv);
        {
            int sn = (s + 1 < 512) ? s + 1 : 511;
            xv = x[(size_t)(sn * 256 + b0 + rr) * 256 + idx];
        }
        __syncthreads();

        // (c) phase A dots
        qdot2(vA2, g_WA, ds, c, ks, gv, rq);
        __syncthreads();
        // (d) phase A combine -> ac in yb
        qcombine(ds, g_bA, yb, c, g);
        __syncthreads();

        // (e) amp gate + cand_t -> vB2[k>=64] (duplicated)
        if (t < 128) {
            const int r = t >> 6, n = t & 63;
            float a0 = yb[r * 512 + n],        a1 = yb[r * 512 + 128 + n];
            float a2 = yb[r * 512 + 256 + n],  a3 = yb[r * 512 + 384 + n];
            float ag = sqrtf(a0 * a0 + a1 * a1 + a2 * a2 + a3 * a3);
            float q0 = yb[r * 512 + 64 + n]  * ag;
            float q1 = yb[r * 512 + 192 + n] * ag;
            float q2 = yb[r * 512 + 320 + n] * ag;
            float q3 = yb[r * 512 + 448 + n] * ag;
            float inv = 1.f / (sqrtf(q0 * q0 + q1 * q1 + q2 * q2 + q3 * q3) + 1e-4f);
            q0 *= inv; q1 *= inv; q2 *= inv; q3 *= inv;
            vB2[(r * 4 + 0) * 128 + 64 + n] = make_float2(q0, q0);
            vB2[(r * 4 + 1) * 128 + 64 + n] = make_float2(q1, q1);
            vB2[(r * 4 + 2) * 128 + 64 + n] = make_float2(q2, q2);
            vB2[(r * 4 + 3) * 128 + 64 + n] = make_float2(q3, q3);
        }
        __syncthreads();

        // (f) phase B dots
        qdot2(vB2, g_WB, ds, c, ks, gv, rq);
        __syncthreads();
        // (g) phase B combine -> upd in yb
        qcombine(ds, g_bB, yb, c, g);
        __syncthreads();

        // (h) gates + new hidden state + output
        if (t < 128) {
            const int r = t >> 6, n = t & 63;
            float u0 = yb[r * 512 + n];
            float u2 = yb[r * 512 + 128 + n];
            float u4 = yb[r * 512 + 256 + n];
            float gh = sqrtf(u0 * u0 + 2.f * u2 * u2 + u4 * u4);   // i reused, k dropped (faithful)
            float u1 = yb[r * 512 + 64 + n],  u3 = yb[r * 512 + 192 + n];
            float u5 = yb[r * 512 + 320 + n], u7 = yb[r * 512 + 448 + n];
            float gc = sqrtf(u1 * u1 + u3 * u3 + u5 * u5 + u7 * u7);
            float* orow = out + (size_t)(s * 256 + b0 + r) * 256;
#pragma unroll
            for (int p = 0; p < 4; ++p) {
                float hn = vB2[(r * 4 + p) * 128 + n].x;        // normalized h
                float ct = vB2[(r * 4 + p) * 128 + 64 + n].x;   // cand_t
                float av = fmaf(hn, gh, ct * gc);
                hb[r * 256 + p * 64 + n] = av;
                orow[p * 64 + n] = av;
            }
            if (writeHT && s == 511) {
#pragma unroll
                for (int p = 0; p < 4; ++p)
                    hT[(size_t)(b0 + r) * 256 + p * 64 + n] = hb[r * 256 + p * 64 + n];
            }
        }
        // no barrier: (h)->(a) hazards are same-thread; cross-thread consumers
        // sit behind the post-(b) barrier of the next step.
    }
}

extern "C" void kernel_launch(void* const* d_in, const int* in_sizes, int n_in,
                              void* d_out, int out_size)
{
    const float* x  = (const float*)d_in[0];
    const float* hx = (const float*)d_in[1];

    qru_prep<<<512, 256>>>(
        (const float*)d_in[2],  (const float*)d_in[3],  (const float*)d_in[4],  (const float*)d_in[5],
        (const float*)d_in[6],  (const float*)d_in[7],  (const float*)d_in[8],  (const float*)d_in[9],
        (const float*)d_in[10], (const float*)d_in[11], (const float*)d_in[12], (const float*)d_in[13],
        (const float*)d_in[14], (const float*)d_in[15], (const float*)d_in[16], (const float*)d_in[17],
        (const float*)d_in[18], (const float*)d_in[19], (const float*)d_in[20], (const float*)d_in[21]);

    float* out = (float*)d_out;
    long long base = 512LL * 256 * 256;
    int writeHT = (out_size >= base + 256 * 256) ? 1 : 0;
    float* hT = out + base;

    size_t smem = (16384 + 2048 + 2048 + 1024 + 512) * sizeof(float);  // 88064 B
    cudaFuncSetAttribute(qru_main, cudaFuncAttributeMaxDynamicSharedMemorySize, (int)smem);
    qru_main<<<128, 512, smem>>>(x, hx, out, hT, writeHT);
}

// round 10
// speedup vs baseline: 1.1872x; 1.1872x over previous
#include <cuda_runtime.h>
#include <cuda_bf16.h>
#include <cstdint>

// QRU forward. R9: x@K_ih hoisted into a tf32 hi/lo mma.sync pre-GEMM (g_XK);
// recurrent kernel = R4 engine with phase A reduced to h_n@K_hh (K=64).

__device__ float g_WHH[4 * 64 * 128];        // phase A recurrent weights [c][k][g]
__device__ float g_WB [4 * 128 * 128];       // phase B: k<64 wpick_h, k>=64 wpick_cand
__device__ float g_bA[512];
__device__ float g_bB[512];
__device__ float g_BHf[512 * 256];           // K_ih^T (signs folded), tf32 hi, [n][k]
__device__ float g_BLf[512 * 256];           // tf32 lo residual
__device__ float g_XK[131072ull * 512];      // x @ K_ih, fp32, row m = s*256+b

__constant__ int   c_M[16] = {0,1,2,3,  1,0,3,2,  2,3,0,1,  3,2,1,0};
__constant__ float c_S[16] = {1.f,-1.f,-1.f,-1.f,  1.f,1.f,-1.f,1.f,
                              1.f,1.f,1.f,-1.f,    1.f,-1.f,1.f,1.f};

__device__ __forceinline__ float tf32r(float v) {
    uint32_t u;
    asm("cvt.rna.tf32.f32 %0, %1;" : "=r"(u) : "f"(v));
    return __uint_as_float(u);
}

// ---------------- prep ------------------------------------------------------
__global__ void qru_prep(
    const float* __restrict__ wih_r, const float* __restrict__ wih_i,
    const float* __restrict__ wih_j, const float* __restrict__ wih_k,
    const float* __restrict__ whh_r, const float* __restrict__ whh_i,
    const float* __restrict__ whh_j, const float* __restrict__ whh_k,
    const float* __restrict__ wpc_r, const float* __restrict__ wpc_i,
    const float* __restrict__ wpc_j, const float* __restrict__ wpc_k,
    const float* __restrict__ wph_r, const float* __restrict__ wph_i,
    const float* __restrict__ wph_j, const float* __restrict__ wph_k,
    const float* __restrict__ b_ih, const float* __restrict__ b_hh,
    const float* __restrict__ b_ph, const float* __restrict__ b_pc)
{
    int i = blockIdx.x * blockDim.x + threadIdx.x;
    if (i < 65536) {                                   // phase B weights
        int cc = i >> 14, k = (i >> 7) & 127, gg = i & 127;
        const float* src;
        if (k < 64) src = (cc == 0 ? wph_r : cc == 1 ? wph_i : cc == 2 ? wph_j : wph_k);
        else        src = (cc == 0 ? wpc_r : cc == 1 ? wpc_i : cc == 2 ? wpc_j : wpc_k);
        g_WB[i] = src[(k & 63) * 128 + gg];
    } else if (i < 98304) {                            // phase A recurrent (w_hh)
        int j = i - 65536;
        int cc = j >> 13, k = (j >> 7) & 63, gg = j & 127;
        const float* src = (cc == 0 ? whh_r : cc == 1 ? whh_i : cc == 2 ? whh_j : whh_k);
        g_WHH[j] = src[k * 128 + gg];
    } else if (i < 229376) {                           // K_ih^T tf32 hi/lo, signs folded
        int j = i - 98304;                             // j = n*256 + k
        int n = j >> 8, k = j & 255;
        int q = n >> 7, gg = n & 127, p = k >> 6, kq = k & 63;
        int cm = c_M[q * 4 + p];
        const float* src = (cm == 0 ? wih_r : cm == 1 ? wih_i : cm == 2 ? wih_j : wih_k);
        float val = c_S[q * 4 + p] * src[kq * 128 + gg];
        float h = tf32r(val);
        g_BHf[j] = h;
        g_BLf[j] = tf32r(val - h);
    } else if (i < 230400) {
        int j = i - 229376;
        if (j < 512) g_bA[j] = b_ih[j] + b_hh[j];
        else         g_bB[j - 512] = b_ph[j - 512] + b_pc[j - 512];
    }
}

// ---------------- pre-GEMM: g_XK = x @ K_ih (tf32 hi/lo, 3 passes) ----------
#define MMA8(d, a, b0, b1)                                                     \
    asm volatile("mma.sync.aligned.m16n8k8.row.col.f32.tf32.tf32.f32 "         \
        "{%0,%1,%2,%3},{%4,%5,%6,%7},{%8,%9},{%0,%1,%2,%3};"                   \
        : "+f"((d)[0]), "+f"((d)[1]), "+f"((d)[2]), "+f"((d)[3])               \
        : "r"((a)[0]), "r"((a)[1]), "r"((a)[2]), "r"((a)[3]),                  \
          "r"(b0), "r"(b1))

__global__ void __launch_bounds__(256, 1)
qru_xk(const float* __restrict__ x)
{
    extern __shared__ float sm[];
    float* Ah = sm;             // [128][68] tf32 hi (pad 4 -> conflict-free frags)
    float* Al = sm + 8704;
    float* Bh = sm + 17408;
    float* Bl = sm + 26112;     // total 34816 floats = 139264 B

    const int t = threadIdx.x;
    const int mt = blockIdx.x >> 2, nt = blockIdx.x & 3;
    const int lane = t & 31, w = t >> 5;
    const int wm = w >> 1, wn = w & 1;       // warp tile: 32m x 64n
    const int gq = lane >> 2, tg = lane & 3;

    float acc[2][8][4];
#pragma unroll
    for (int f = 0; f < 2; ++f)
#pragma unroll
        for (int nf = 0; nf < 8; ++nf)
#pragma unroll
            for (int i = 0; i < 4; ++i) acc[f][nf][i] = 0.f;

    for (int kc = 0; kc < 4; ++kc) {         // K chunks of 64
        for (int u = t; u < 2048; u += 256) {
            int r = u >> 4, q4 = u & 15;
            float4 a = ((const float4*)x)[(size_t)(mt * 128 + r) * 64 + kc * 16 + q4];
            float hxv = tf32r(a.x), hyv = tf32r(a.y), hzv = tf32r(a.z), hwv = tf32r(a.w);
            float* pa = Ah + r * 68 + q4 * 4;
            pa[0] = hxv; pa[1] = hyv; pa[2] = hzv; pa[3] = hwv;
            float* pl = Al + r * 68 + q4 * 4;
            pl[0] = tf32r(a.x - hxv); pl[1] = tf32r(a.y - hyv);
            pl[2] = tf32r(a.z - hzv); pl[3] = tf32r(a.w - hwv);
            float4 bh = ((const float4*)g_BHf)[(size_t)(nt * 128 + r) * 64 + kc * 16 + q4];
            float4 bl = ((const float4*)g_BLf)[(size_t)(nt * 128 + r) * 64 + kc * 16 + q4];
            float* pb = Bh + r * 68 + q4 * 4;
            pb[0] = bh.x; pb[1] = bh.y; pb[2] = bh.z; pb[3] = bh.w;
            float* pc = Bl + r * 68 + q4 * 4;
            pc[0] = bl.x; pc[1] = bl.y; pc[2] = bl.z; pc[3] = bl.w;
        }
        __syncthreads();

        for (int pass = 0; pass < 3; ++pass) {      // hh, hl, lh
            const float* As = (pass == 2) ? Al : Ah;
            const float* Bs = (pass == 1) ? Bl : Bh;
#pragma unroll
            for (int ks = 0; ks < 8; ++ks) {
                const int k0 = ks * 8;
                uint32_t af[2][4];
#pragma unroll
                for (int f = 0; f < 2; ++f) {
                    const uint32_t* ap = (const uint32_t*)
                        (As + (wm * 32 + f * 16 + gq) * 68 + k0 + tg);
                    af[f][0] = ap[0];
                    af[f][1] = ap[8 * 68];
                    af[f][2] = ap[4];
                    af[f][3] = ap[8 * 68 + 4];
                }
#pragma unroll
                for (int nf = 0; nf < 8; ++nf) {
                    const uint32_t* bp = (const uint32_t*)
                        (Bs + (wn * 64 + nf * 8 + gq) * 68 + k0 + tg);
                    uint32_t b0 = bp[0], b1 = bp[4];
                    MMA8(acc[0][nf], af[0], b0, b1);
                    MMA8(acc[1][nf], af[1], b0, b1);
                }
            }
        }
        __syncthreads();
    }
#pragma unroll
    for (int f = 0; f < 2; ++f)
#pragma unroll
        for (int nf = 0; nf < 8; ++nf) {
            int row = mt * 128 + wm * 32 + f * 16 + gq;
            int col = nt * 128 + wn * 64 + nf * 8 + 2 * tg;
            *(float2*)&g_XK[(size_t)row * 512 + col] =
                make_float2(acc[f][nf][0], acc[f][nf][1]);
            *(float2*)&g_XK[(size_t)(row + 8) * 512 + col] =
                make_float2(acc[f][nf][2], acc[f][nf][3]);
        }
}

// ---------------- recurrent kernel (R8 structure, verified) -----------------
__device__ __forceinline__ void qdotA(const float* __restrict__ v,   // [2][4][64]
                                      float* __restrict__ ds,
                                      int c, int ks, int r, int gv)
{
    float acc[4][4];
#pragma unroll
    for (int p = 0; p < 4; ++p)
#pragma unroll
        for (int i = 0; i < 4; ++i) acc[p][i] = 0.f;

    const float4* Wp = reinterpret_cast<const float4*>(g_WHH) + (c * 64 + ks * 32) * 32 + gv;
    const float* vb = v + r * 256 + ks * 32;

#pragma unroll 2
    for (int kb = 0; kb < 32; kb += 4) {
        float4 w0 = Wp[0], w1 = Wp[32], w2 = Wp[64], w3 = Wp[96];
        Wp += 128;
#pragma unroll
        for (int p = 0; p < 4; ++p) {
            const float4 vv = *reinterpret_cast<const float4*>(vb + p * 64 + kb);
            float* a = acc[p];
            a[0] = fmaf(vv.x, w0.x, a[0]); a[1] = fmaf(vv.x, w0.y, a[1]);
            a[2] = fmaf(vv.x, w0.z, a[2]); a[3] = fmaf(vv.x, w0.w, a[3]);
            a[0] = fmaf(vv.y, w1.x, a[0]); a[1] = fmaf(vv.y, w1.y, a[1]);
            a[2] = fmaf(vv.y, w1.z, a[2]); a[3] = fmaf(vv.y, w1.w, a[3]);
            a[0] = fmaf(vv.z, w2.x, a[0]); a[1] = fmaf(vv.z, w2.y, a[1]);
            a[2] = fmaf(vv.z, w2.z, a[2]); a[3] = fmaf(vv.z, w2.w, a[3]);
            a[0] = fmaf(vv.w, w3.x, a[0]); a[1] = fmaf(vv.w, w3.y, a[1]);
            a[2] = fmaf(vv.w, w3.z, a[2]); a[3] = fmaf(vv.w, w3.w, a[3]);
        }
    }
#pragma unroll
    for (int p = 0; p < 4; ++p)
        *reinterpret_cast<float4*>(ds + (p * 4 + c) * 512 + ks * 256 + r * 128 + gv * 4)
            = make_float4(acc[p][0], acc[p][1], acc[p][2], acc[p][3]);
}

__device__ __forceinline__ void qdotB(const float* __restrict__ v,   // [2][4][128]
                                      float* __restrict__ ds,
                                      int c, int ks, int gv)
{
    float acc[4][2][4];
#pragma unroll
    for (int p = 0; p < 4; ++p)
#pragma unroll
        for (int r = 0; r < 2; ++r)
#pragma unroll
            for (int i = 0; i < 4; ++i) acc[p][r][i] = 0.f;

    const float4* Wp = reinterpret_cast<const float4*>(g_WB) + (c * 128 + ks * 32) * 32 + gv;
    const int k0 = ks * 32;

#pragma unroll 2
    for (int kb = 0; kb < 32; kb += 4) {
        float4 w0 = Wp[0], w1 = Wp[32], w2 = Wp[64], w3 = Wp[96];
        Wp += 128;
#pragma unroll
        for (int p = 0; p < 4; ++p)
#pragma unroll
            for (int r = 0; r < 2; ++r) {
                const float4 vv = *reinterpret_cast<const float4*>(v + (r * 4 + p) * 128 + k0 + kb);
                float* a = acc[p][r];
                a[0] = fmaf(vv.x, w0.x, a[0]); a[1] = fmaf(vv.x, w0.y, a[1]);
                a[2] = fmaf(vv.x, w0.z, a[2]); a[3] = fmaf(vv.x, w0.w, a[3]);
                a[0] = fmaf(vv.y, w1.x, a[0]); a[1] = fmaf(vv.y, w1.y, a[1]);
                a[2] = fmaf(vv.y, w1.z, a[2]); a[3] = fmaf(vv.y, w1.w, a[3]);
                a[0] = fmaf(vv.z, w2.x, a[0]); a[1] = fmaf(vv.z, w2.y, a[1]);
                a[2] = fmaf(vv.z, w2.z, a[2]); a[3] = fmaf(vv.z, w2.w, a[3]);
                a[0] = fmaf(vv.w, w3.x, a[0]); a[1] = fmaf(vv.w, w3.y, a[1]);
                a[2] = fmaf(vv.w, w3.z, a[2]); a[3] = fmaf(vv.w, w3.w, a[3]);
            }
    }
#pragma unroll
    for (int p = 0; p < 4; ++p)
#pragma unroll
        for (int r = 0; r < 2; ++r)
            *reinterpret_cast<float4*>(ds + (p * 4 + c) * 1024 + ks * 256 + r * 128 + gv * 4)
                = make_float4(acc[p][r][0], acc[p][r][1], acc[p][r][2], acc[p][r][3]);
}

__global__ void __launch_bounds__(512, 1)
qru_main(const float* __restrict__ hx,
         float* __restrict__ out, float* __restrict__ hT, int writeHT)
{
    extern __shared__ float smf[];
    float* ds = smf;              // 16384 (phase A uses first 8192)
    float* vA = smf + 16384;      //   512 : [r][p][64] h_n
    float* vB = smf + 16896;      //  1024 : [r][p][128] = [h_n | cand_t]
    float* yb = smf + 17920;      //  1024
    float* hb = smf + 18944;      //   512

    const int t   = threadIdx.x;
    const int b0  = blockIdx.x * 2;
    const int c   = t >> 7;
    const int ksA = (t >> 6) & 1;
    const int rA  = (t >> 5) & 1;
    const int gvA = t & 31;
    const int ksB = (t >> 5) & 3;
    const int gvB = t & 31;
    const int g   = t & 127;
    const int rr  = t >> 8;
    const int idx = t & 255;

    hb[rr * 256 + idx] = hx[(b0 + rr) * 256 + idx];
    __syncthreads();

    const float* xk0p = g_XK + (size_t)b0 * 512 + t;

    for (int s = 0; s < 512; ++s) {
        const float* xkp = xk0p + (size_t)s * 256 * 512;
        float xk0 = xkp[0];
        float xk1 = xkp[512];

        if (t < 128) {
            const int r = t >> 6, n = t & 63;
            float h0 = hb[r * 256 + n],        h1 = hb[r * 256 + 64 + n];
            float h2 = hb[r * 256 + 128 + n],  h3 = hb[r * 256 + 192 + n];
            float inv = 1.f / (sqrtf(h0 * h0 + h1 * h1 + h2 * h2 + h3 * h3) + 1e-4f);
            h0 *= inv; h1 *= inv; h2 *= inv; h3 *= inv;
            vA[r * 256 + n]       = h0;  vA[r * 256 + 64 + n]  = h1;
            vA[r * 256 + 128 + n] = h2;  vA[r * 256 + 192 + n] = h3;
            vB[(r * 4 + 0) * 128 + n] = h0;  vB[(r * 4 + 1) * 128 + n] = h1;
            vB[(r * 4 + 2) * 128 + n] = h2;  vB[(r * 4 + 3) * 128 + n] = h3;
        }
        __syncthreads();

        qdotA(vA, ds, c, ksA, rA, gvA);
        __syncthreads();

        {
            float xk[2] = {xk0, xk1};
#pragma unroll
            for (int r = 0; r < 2; ++r) {
                float y = xk[r] + g_bA[c * 128 + g];
#pragma unroll
                for (int p = 0; p < 4; ++p) {
                    const int   cm = c_M[c * 4 + p];
                    const float sg = c_S[c * 4 + p];
                    const float* dp = ds + (p * 4 + cm) * 512 + r * 128 + g;
                    y = fmaf(sg, dp[0] + dp[256], y);
                }
                yb[r * 512 + c * 128 + g] = y;
            }
        }
        __syncthreads();

        if (t < 128) {
            const int r = t >> 6, n = t & 63;
            float a0 = yb[r * 512 + n],        a1 = yb[r * 512 + 128 + n];
            float a2 = yb[r * 512 + 256 + n],  a3 = yb[r * 512 + 384 + n];
            float ag = sqrtf(a0 * a0 + a1 * a1 + a2 * a2 + a3 * a3);
            float q0 = yb[r * 512 + 64 + n]  * ag;
            float q1 = yb[r * 512 + 192 + n] * ag;
            float q2 = yb[r * 512 + 320 + n] * ag;
            float q3 = yb[r * 512 + 448 + n] * ag;
            float inv = 1.f / (sqrtf(q0 * q0 + q1 * q1 + q2 * q2 + q3 * q3) + 1e-4f);
            vB[(r * 4 + 0) * 128 + 64 + n] = q0 * inv;
            vB[(r * 4 + 1) * 128 + 64 + n] = q1 * inv;
            vB[(r * 4 + 2) * 128 + 64 + n] = q2 * inv;
            vB[(r * 4 + 3) * 128 + 64 + n] = q3 * inv;
        }
        __syncthreads();

        qdotB(vB, ds, c, ksB, gvB);
        __syncthreads();

#pragma unroll
        for (int r = 0; r < 2; ++r) {
            float y = g_bB[c * 128 + g];
#pragma unroll
            for (int p = 0; p < 4; ++p) {
                const int   cm = c_M[c * 4 + p];
                const float sg = c_S[c * 4 + p];
                const float* dp = ds + (p * 4 + cm) * 1024 + r * 128 + g;
                y = fmaf(sg, dp[0] + dp[256] + dp[512] + dp[768], y);
            }
            yb[r * 512 + c * 128 + g] = y;
        }
        __syncthreads();

        if (t < 128) {
            const int r = t >> 6, n = t & 63;
            float u0 = yb[r * 512 + n];
            float u2 = yb[r * 512 + 128 + n];
            float u4 = yb[r * 512 + 256 + n];
            float gh = sqrtf(u0 * u0 + 2.f * u2 * u2 + u4 * u4);   // faithful gate
            float u1 = yb[r * 512 + 64 + n],  u3 = yb[r * 512 + 192 + n];
            float u5 = yb[r * 512 + 320 + n], u7 = yb[r * 512 + 448 + n];
            float gc = sqrtf(u1 * u1 + u3 * u3 + u5 * u5 + u7 * u7);
            float* orow = out + (size_t)(s * 256 + b0 + r) * 256;
#pragma unroll
            for (int p = 0; p < 4; ++p) {
                float hn = vB[(r * 4 + p) * 128 + n];
                float ct = vB[(r * 4 + p) * 128 + 64 + n];
                float av = fmaf(hn, gh, ct * gc);
                hb[r * 256 + p * 64 + n] = av;
                orow[p * 64 + n] = av;
            }
            if (writeHT && s == 511)
#pragma unroll
                for (int p = 0; p < 4; ++p)
                    hT[(size_t)(b0 + r) * 256 + p * 64 + n] = hb[r * 256 + p * 64 + n];
        }
    }
}

extern "C" void kernel_launch(void* const* d_in, const int* in_sizes, int n_in,
                              void* d_out, int out_size)
{
    const float* x  = (const float*)d_in[0];
    const float* hx = (const float*)d_in[1];

    qru_prep<<<900, 256>>>(
        (const float*)d_in[2],  (const float*)d_in[3],  (const float*)d_in[4],  (const float*)d_in[5],
        (const float*)d_in[6],  (const float*)d_in[7],  (const float*)d_in[8],  (const float*)d_in[9],
        (const float*)d_in[10], (const float*)d_in[11], (const float*)d_in[12], (const float*)d_in[13],
        (const float*)d_in[14], (const float*)d_in[15], (const float*)d_in[16], (const float*)d_in[17],
        (const float*)d_in[18], (const float*)d_in[19], (const float*)d_in[20], (const float*)d_in[21]);

    size_t smx = 34816 * sizeof(float);                  // 139264 B
    cudaFuncSetAttribute(qru_xk, cudaFuncAttributeMaxDynamicSharedMemorySize, (int)smx);
    qru_xk<<<4096, 256, smx>>>(x);

    float* out = (float*)d_out;
    long long base = 512LL * 256 * 256;
    int writeHT = (out_size >= base + 256 * 256) ? 1 : 0;
    float* hT = out + base;

    size_t smm = (16384 + 512 + 1024 + 1024 + 512) * sizeof(float);  // 77824 B
    cudaFuncSetAttribute(qru_main, cudaFuncAttributeMaxDynamicSharedMemorySize, (int)smm);
    qru_main<<<128, 512, smm>>>(hx, out, hT, writeHT);
}